// round 1
// baseline (speedup 1.0000x reference)
#include <cuda_runtime.h>

#define NEGF (-1e30f)
#define MAXB 4096

__device__ float g_loss[MAXB];

__device__ __forceinline__ float lae(float x, float y) {
    float m = fmaxf(x, y);
    return m + __logf(__expf(x - m) + __expf(y - m));
}

__global__ void __launch_bounds__(512) ctc_alpha_kernel(
    const float* __restrict__ log_probs,   // [B, T, V]
    const int*   __restrict__ in_len,      // [B]
    const int*   __restrict__ targets,     // [B, S]
    const int*   __restrict__ tgt_len,     // [B]
    int T, int V, int S)
{
    extern __shared__ float smem[];
    const int L2cap = 2 * S + 1;
    float* sa  = smem;               // [L2cap + 2], sa[2+s] = alpha[s], sa[0..1] = NEG pad
    float* lpb = smem + L2cap + 2;   // [2*V] double-buffered log-prob rows

    const int b   = blockIdx.x;
    const int tid = threadIdx.x;
    const int bd  = blockDim.x;

    const int L   = tgt_len[b];
    int Tin = in_len[b];
    if (Tin > T) Tin = T;
    if (Tin < 1) Tin = 1;
    const int L2  = 2 * L + 1;

    const float* lp = log_probs + (size_t)b * T * V;
    const int*   tg = targets   + (size_t)b * S;

    // init all shared alpha slots (incl. pad) to NEG
    for (int i = tid; i < L2cap + 2; i += bd) sa[i] = NEGF;

    // per-thread positions: s0 = tid, s1 = tid + bd
    const int s0 = tid, s1 = tid + bd;
    int  lab0 = 0, lab1 = 0;
    bool sk0 = false, sk1 = false;
    const bool v0 = (s0 < L2), v1 = (s1 < L2);
    if (v0 && (s0 & 1)) { lab0 = tg[(s0 - 1) >> 1]; if (s0 >= 3) sk0 = (lab0 != tg[(s0 - 3) >> 1]); }
    if (v1 && (s1 & 1)) { lab1 = tg[(s1 - 1) >> 1]; if (s1 >= 3) sk1 = (lab1 != tg[(s1 - 3) >> 1]); }

    // alpha at t=0
    float a0 = NEGF, a1 = NEGF;
    if (v0) {
        if (s0 == 0)      a0 = lp[0];       // blank
        else if (s0 == 1) a0 = lp[lab0];    // first label (valid since L2 > 1 => L > 0)
    }
    // s1 >= bd >= 512 > 1 : stays NEG at t=0

    __syncthreads();   // NEG init complete before targeted writes
    if (v0) sa[2 + s0] = a0;
    if (v1) sa[2 + s1] = a1;

    // preload log-prob row t=1 into buffer (1 & 1) = 1
    if (Tin > 1) {
        const float* src = lp + (size_t)V;
        for (int i = tid; i < V; i += bd) lpb[V + i] = src[i];
    }
    __syncthreads();

    for (int t = 1; t < Tin; ++t) {
        const float* lr = lpb + (t & 1) * V;
        float n0 = NEGF, n1 = NEGF;
        if (v0) {
            float x = lae(a0, sa[1 + s0]);
            if (sk0) x = lae(x, sa[s0]);
            n0 = x + lr[lab0];
        }
        if (v1) {
            float x = lae(a1, sa[1 + s1]);
            if (sk1) x = lae(x, sa[s1]);
            n1 = x + lr[lab1];
        }
        // prefetch next row into the other buffer (it is not read this step)
        if (t + 1 < Tin) {
            const float* src = lp + (size_t)(t + 1) * V;
            float* dst = lpb + ((t + 1) & 1) * V;
            for (int i = tid; i < V; i += bd) dst[i] = src[i];
        }
        __syncthreads();   // all reads of sa / lr done
        a0 = n0; a1 = n1;
        if (v0) sa[2 + s0] = a0;
        if (v1) sa[2 + s1] = a1;
        __syncthreads();   // new alpha visible
    }

    if (tid == 0) {
        float a_blank = sa[2 + 2 * L];
        float a_label = (L > 0) ? sa[1 + 2 * L] : NEGF;
        float ll = lae(a_blank, a_label);
        float loss = -ll;
        if (loss > 1e29f) loss = 0.0f;          // zero_infinity
        int Lm = (L > 0) ? L : 1;
        g_loss[b] = loss / (float)Lm;           // reduction='mean' per-sample scaling
    }
}

__global__ void ctc_reduce_kernel(float* __restrict__ out, int B) {
    // single-thread, fixed-order sum => bitwise deterministic
    float s = 0.0f;
    for (int i = 0; i < B; ++i) s += g_loss[i];
    out[0] = s / (float)B;
}

extern "C" void kernel_launch(void* const* d_in, const int* in_sizes, int n_in,
                              void* d_out, int out_size) {
    const float* log_probs = (const float*)d_in[0];
    const int*   in_len    = (const int*)d_in[1];
    const int*   targets   = (const int*)d_in[2];
    const int*   tgt_len   = (const int*)d_in[3];

    const int B = in_sizes[1];                  // log_probs_length has B elements
    const int S = in_sizes[2] / B;              // text_encoded is [B, S]
    const int V = 128;
    const int T = in_sizes[0] / (B * V);        // log_probs is [B, T, V]

    const size_t smem = (size_t)((2 * S + 3) + 2 * V) * sizeof(float);
    ctc_alpha_kernel<<<B, 512, smem>>>(log_probs, in_len, targets, tgt_len, T, V, S);
    ctc_reduce_kernel<<<1, 1>>>((float*)d_out, B);
}

// round 3
// speedup vs baseline: 1.8962x; 1.8962x over previous
#include <cuda_runtime.h>

#define NEGF (-1e30f)
#define MAXB 4096
__device__ float g_loss[MAXB];

__global__ void __launch_bounds__(544) ctc_fwd_kernel(
    const float* __restrict__ log_probs,   // [B, T, V]
    const int*   __restrict__ in_len,      // [B]
    const int*   __restrict__ targets,     // [B, S]
    const int*   __restrict__ tgt_len,     // [B]
    int T, int V, int S)
{
    extern __shared__ float smem[];
    const int L2cap = 2 * S + 1;
    const int BUF   = L2cap + 2;           // 2-slot front pad (always NEG)
    float* buf0 = smem;
    float* buf1 = smem + BUF;

    const int b   = blockIdx.x;
    const int tid = threadIdx.x;

    const int L = tgt_len[b];
    int Tin = in_len[b];
    if (Tin > T) Tin = T;
    if (Tin < 1) Tin = 1;
    const int L2 = 2 * L + 1;

    const float* lp = log_probs + (size_t)b * T * V;
    const int*   tg = targets   + (size_t)b * S;

    const int  s   = tid;
    const bool act = (s < L2);
    int  lab = 0;
    bool sk  = false;
    if (act && (s & 1)) {
        lab = tg[(s - 1) >> 1];
        if (s >= 3) sk = (lab != tg[(s - 3) >> 1]);
    }

    // init both buffers (incl. pads) to NEG
    for (int i = tid; i < 2 * BUF; i += blockDim.x) smem[i] = NEGF;

    // alpha at t = 0 (log space)
    float a = NEGF;
    if (act) {
        if (s == 0)      a = lp[0];        // blank
        else if (s == 1) a = lp[lab];      // first label (L > 0 since L2 > 1)
    }
    __syncthreads();                       // NEG init complete
    if (act) buf0[2 + s] = a;

    // register prefetch ring: ring[k] = lp[t*V + lab] for t = tb + k
    float ring[8];
    #pragma unroll
    for (int k = 0; k < 8; ++k) {
        int t = 1 + k;
        ring[k] = (act && t < Tin) ? lp[(size_t)t * V + lab] : 0.0f;
    }
    __syncthreads();                       // buf0 visible

    int curb = 0;
    for (int tb = 1; tb < Tin; tb += 8) {
        #pragma unroll
        for (int k = 0; k < 8; ++k) {
            const int t = tb + k;
            if (t < Tin) {                 // uniform across block
                float* bo = curb ? buf1 : buf0;
                float* bn = curb ? buf0 : buf1;
                if (act) {
                    const float lpv = ring[k];
                    const int tn = t + 8;
                    if (tn < Tin) ring[k] = lp[(size_t)tn * V + lab]; // 8-deep prefetch
                    // fused 3-way logaddexp: a, alpha[s-1], (skip) alpha[s-2]
                    float y = bo[1 + s];
                    float z = sk ? bo[s] : NEGF;
                    float m = fmaxf(a, y);
                    if (sk) m = fmaxf(m, z);
                    float sum = __expf(a - m) + __expf(y - m);
                    if (sk) sum += __expf(z - m);
                    a = m + __logf(sum) + lpv;
                    bn[2 + s] = a;
                }
                curb ^= 1;
                __syncthreads();
            }
        }
    }

    if (tid == 0) {
        float* bc = curb ? buf1 : buf0;
        float x = bc[2 + 2 * L];                     // alpha[2L] (blank)
        float y = (L > 0) ? bc[1 + 2 * L] : NEGF;    // alpha[2L-1]
        float m = fmaxf(x, y);
        float ll = m + __logf(__expf(x - m) + __expf(y - m));
        float loss = -ll;
        if (!(loss <= 1e29f)) loss = 0.0f;           // zero_infinity (+ nan guard)
        int Lm = (L > 0) ? L : 1;
        g_loss[b] = loss / (float)Lm;
    }
}

__global__ void ctc_reduce_kernel(float* __restrict__ out, int B) {
    // single warp, fixed shuffle tree => deterministic
    int lane = threadIdx.x;
    float s = 0.0f;
    for (int i = lane; i < B; i += 32) s += g_loss[i];
    #pragma unroll
    for (int off = 16; off; off >>= 1)
        s += __shfl_xor_sync(0xffffffffu, s, off);
    if (lane == 0) out[0] = s / (float)B;
}

extern "C" void kernel_launch(void* const* d_in, const int* in_sizes, int n_in,
                              void* d_out, int out_size) {
    const float* log_probs = (const float*)d_in[0];
    const int*   in_len    = (const int*)d_in[1];
    const int*   targets   = (const int*)d_in[2];
    const int*   tgt_len   = (const int*)d_in[3];

    const int B = in_sizes[1];
    const int S = in_sizes[2] / B;
    const int V = 128;
    const int T = in_sizes[0] / (B * V);

    const int L2cap = 2 * S + 1;
    const size_t smem = (size_t)(2 * (L2cap + 2)) * sizeof(float);
    ctc_fwd_kernel<<<B, 544, smem>>>(log_probs, in_len, targets, tgt_len, T, V, S);
    ctc_reduce_kernel<<<1, 32>>>((float*)d_out, B);
}

// round 4
// speedup vs baseline: 1.9636x; 1.0356x over previous
#include <cuda_runtime.h>

#define NEGF  (-1e30f)
#define LOG2E (1.4426950408889634f)
#define LN2   (0.6931471805599453f)
#define MAXB  4096
__device__ float g_loss[MAXB];

__device__ __forceinline__ float ex2f_(float x){ float y; asm("ex2.approx.f32 %0,%1;":"=f"(y):"f"(x)); return y; }
__device__ __forceinline__ float lg2f_(float x){ float y; asm("lg2.approx.f32 %0,%1;":"=f"(y):"f"(x)); return y; }

// 2-way logaddexp, base 2: 1 EX2 + 1 LG2
__device__ __forceinline__ float lae2(float x, float y) {
    float m = fmaxf(x, y);
    float d = -fabsf(x - y);
    return m + lg2f_(1.0f + ex2f_(d));
}
// 3-way logaddexp, base 2 (fused): 3 EX2 + 1 LG2
__device__ __forceinline__ float lae3(float x, float y, float z) {
    float m = fmaxf(fmaxf(x, y), z);
    float t = ex2f_(x - m) + ex2f_(y - m) + ex2f_(z - m);
    return m + lg2f_(t);
}

// One thread owns extended positions 2j (blank) and 2j+1 (label tg[j]).
// Shared carries only the odd alphas (a1); everything else is register-resident.
__global__ void __launch_bounds__(288) ctc_fwd_kernel(
    const float* __restrict__ log_probs,   // [B, T, V]
    const int*   __restrict__ in_len,      // [B]
    const int*   __restrict__ targets,     // [B, S]
    const int*   __restrict__ tgt_len,     // [B]
    int T, int V, int S)
{
    extern __shared__ float smem[];
    const int BUF = S + 2;                 // slot 0 = left pad (NEG forever)
    float* buf0 = smem;                    // a1[j] at index 1+j
    float* buf1 = smem + BUF;

    const int b   = blockIdx.x;
    const int j   = threadIdx.x;

    const int L = tgt_len[b];
    int Tin = in_len[b];
    if (Tin > T) Tin = T;
    if (Tin < 1) Tin = 1;

    const float* lp = log_probs + (size_t)b * T * V;
    const int*   tg = targets   + (size_t)b * S;

    const bool act  = (j <= L) && (2 * j < 2 * S + 1);   // position 2j valid
    const bool act1 = (j <  L);                          // position 2j+1 valid
    int  lab = 0;
    bool sk  = false;
    if (act1) {
        lab = tg[j];
        if (j >= 1) sk = (lab != tg[j - 1]);
    }

    // init both buffers (incl. pads) to NEG
    for (int i = j; i < 2 * BUF; i += blockDim.x) smem[i] = NEGF;

    // t = 0 (log2 space)
    float a0 = NEGF, a1 = NEGF;
    if (j == 0) {
        a0 = lp[0] * LOG2E;
        if (L > 0) a1 = lp[lab] * LOG2E;
    }
    __syncthreads();
    if (act) buf0[1 + j] = a1;

    // prefetch rings: blank lp (broadcast) + own label lp, 8 steps deep
    float ring_b[8], ring_l[8];
    #pragma unroll
    for (int k = 0; k < 8; ++k) {
        int t = 1 + k;
        if (act && t < Tin) {
            ring_b[k] = lp[(size_t)t * V];
            ring_l[k] = lp[(size_t)t * V + lab];
        } else { ring_b[k] = 0.0f; ring_l[k] = 0.0f; }
    }
    __syncthreads();

    float* bo = buf0;
    float* bn = buf1;
    for (int tb = 1; tb < Tin; tb += 8) {
        #pragma unroll
        for (int k = 0; k < 8; ++k) {
            const int t = tb + k;
            if (t < Tin) {                 // uniform per block
                if (act) {
                    const float bl = ring_b[k] * LOG2E;
                    const float lv = ring_l[k] * LOG2E;
                    const int tn = t + 8;
                    if (tn < Tin) {        // 8-deep refill
                        ring_b[k] = lp[(size_t)tn * V];
                        ring_l[k] = lp[(size_t)tn * V + lab];
                    }
                    const float o = bo[j];               // left neighbor's odd alpha
                    float n0 = lae2(a0, o) + bl;          // blank at 2j
                    float zz = sk ? o : NEGF;
                    float n1 = lae3(a1, a0, zz) + lv;     // label at 2j+1
                    a0 = n0;
                    a1 = act1 ? n1 : NEGF;
                    bn[1 + j] = a1;
                }
                float* tmp = bo; bo = bn; bn = tmp;
                __syncthreads();
            }
        }
    }

    // publish a0 (even alphas) into the free buffer for the final gather
    if (act) bn[1 + j] = a0;
    __syncthreads();

    if (j == 0) {
        float x = bn[1 + L];                       // alpha[2L]   (blank)
        float y = (L > 0) ? bo[L] : NEGF;          // alpha[2L-1] = a1 of thread L-1
        float ll2 = lae2(x, y);
        float loss = -ll2 * LN2;
        if (!(loss <= 1e29f)) loss = 0.0f;         // zero_infinity (+ nan guard)
        int Lm = (L > 0) ? L : 1;
        g_loss[b] = loss / (float)Lm;
    }
}

__global__ void ctc_reduce_kernel(float* __restrict__ out, int B) {
    int lane = threadIdx.x;
    float s = 0.0f;
    for (int i = lane; i < B; i += 32) s += g_loss[i];
    #pragma unroll
    for (int off = 16; off; off >>= 1)
        s += __shfl_xor_sync(0xffffffffu, s, off);
    if (lane == 0) out[0] = s / (float)B;
}

extern "C" void kernel_launch(void* const* d_in, const int* in_sizes, int n_in,
                              void* d_out, int out_size) {
    const float* log_probs = (const float*)d_in[0];
    const int*   in_len    = (const int*)d_in[1];
    const int*   targets   = (const int*)d_in[2];
    const int*   tgt_len   = (const int*)d_in[3];

    const int B = in_sizes[1];
    const int S = in_sizes[2] / B;
    const int V = 128;
    const int T = in_sizes[0] / (B * V);

    const size_t smem = (size_t)(2 * (S + 2)) * sizeof(float);
    ctc_fwd_kernel<<<B, 288, smem>>>(log_probs, in_len, targets, tgt_len, T, V, S);
    ctc_reduce_kernel<<<1, 32>>>((float*)d_out, B);
}